// round 9
// baseline (speedup 1.0000x reference)
#include <cuda_runtime.h>
#include <cuda_fp16.h>
#include <cstdint>
#include <cstddef>

// ---------------- problem constants ----------------
#define B_ROWS 4096
#define C_ROWS 65536
#define DIM    1024
#define TOPK   5

// ---------------- hybrid GEMM tiling ----------------
#define BM   128
#define BNT  128                 // tensor-core columns per CTA
#define BNS  64                  // SIMT (HFMA2) columns per CTA
#define BNC  (BNT + BNS)         // 192
#define BK   32
#define NKI  (DIM / BK)          // 32
#define NT   342                 // ceil(65536/192)
#define CAND_PER_TILE 8
#define CAND_PER_ROW (NT * CAND_PER_TILE)   // 2736
#define RESCORE 16

#define SROW 40                              // halfs per smem row (conflict-free pad)
#define AB_BYTES (BM * SROW * 2)             // 10240 (A tile; B tile same)
#define BP_BYTES 4096                        // B' tile: [k2 0..15][n 0..63] half2
#define STAGE (2 * AB_BYTES + BP_BYTES)      // 24576
#define CSTR 196
#define SMEM_BYTES (BM * CSTR * 4)           // 100352 (> 2*STAGE = 49152)

// ---------------- device scratch ----------------
__device__ __align__(16) __half g_memh[(size_t)C_ROWS * DIM]; // normalized fp16 memory
__device__ __align__(16) __half g_xh[(size_t)B_ROWS * DIM];   // normalized fp16 x
__device__ float g_minv[C_ROWS];
__device__ float g_xinv[B_ROWS];
__device__ __align__(16) float g_cv[(size_t)B_ROWS * CAND_PER_ROW];
__device__ __align__(16) int   g_ci[(size_t)B_ROWS * CAND_PER_ROW];

// ---------------- PTX helpers ----------------
__device__ __forceinline__ void cp16(uint32_t saddr, const void* gaddr) {
    asm volatile("cp.async.cg.shared.global [%0], [%1], 16;" :: "r"(saddr), "l"(gaddr));
}
__device__ __forceinline__ void cp_commit() {
    asm volatile("cp.async.commit_group;" ::: "memory");
}
__device__ __forceinline__ void ldsm4(uint32_t (&r)[4], uint32_t addr) {
    asm volatile("ldmatrix.sync.aligned.m8n8.x4.shared.b16 {%0,%1,%2,%3}, [%4];"
                 : "=r"(r[0]), "=r"(r[1]), "=r"(r[2]), "=r"(r[3]) : "r"(addr));
}
__device__ __forceinline__ void mma16816(float (&c)[4], const uint32_t (&a)[4],
                                         uint32_t b0, uint32_t b1) {
    asm volatile(
        "mma.sync.aligned.m16n8k16.row.col.f32.f16.f16.f32 "
        "{%0,%1,%2,%3},{%4,%5,%6,%7},{%8,%9},{%0,%1,%2,%3};"
        : "+f"(c[0]), "+f"(c[1]), "+f"(c[2]), "+f"(c[3])
        : "r"(a[0]), "r"(a[1]), "r"(a[2]), "r"(a[3]), "r"(b0), "r"(b1));
}
__device__ __forceinline__ uint4 lds128(uint32_t addr) {
    uint4 r;
    asm volatile("ld.shared.v4.u32 {%0,%1,%2,%3}, [%4];"
                 : "=r"(r.x), "=r"(r.y), "=r"(r.z), "=r"(r.w) : "r"(addr));
    return r;
}
__device__ __forceinline__ uint32_t lds32(uint32_t addr) {
    uint32_t r;
    asm volatile("ld.shared.b32 %0, [%1];" : "=r"(r) : "r"(addr));
    return r;
}
__device__ __forceinline__ void sts32(uint32_t addr, uint32_t v) {
    asm volatile("st.shared.b32 [%0], %1;" :: "r"(addr), "r"(v));
}
__device__ __forceinline__ __half2 u2h2(uint32_t u) {
    return *reinterpret_cast<__half2*>(&u);
}

// ---------------- fused prep: warp-per-row, fp16 normalized ----------------
__global__ __launch_bounds__(256) void prep_all_kernel(const float* __restrict__ mem,
                                                       const float* __restrict__ x) {
    const int gw = blockIdx.x * 8 + (threadIdx.x >> 5);
    const int lane = threadIdx.x & 31;
    const bool is_mem = (gw < C_ROWS);
    const int row = is_mem ? gw : gw - C_ROWS;
    if (!is_mem && row >= B_ROWS) return;

    const float* src = is_mem ? (mem + (size_t)row * DIM) : (x + (size_t)row * DIM);
    const float4* s4 = reinterpret_cast<const float4*>(src);

    float4 v[8];
    float ss = 0.f;
    #pragma unroll
    for (int j = 0; j < 8; j++) {
        v[j] = s4[lane + 32 * j];
        ss += v[j].x * v[j].x + v[j].y * v[j].y + v[j].z * v[j].z + v[j].w * v[j].w;
    }
    #pragma unroll
    for (int o = 16; o; o >>= 1) ss += __shfl_xor_sync(0xffffffffu, ss, o);
    float iv = 1.0f / fmaxf(sqrtf(ss), 1e-12f);
    if (lane == 0) {
        if (is_mem) g_minv[row] = iv;
        else        g_xinv[row] = iv;
    }
    __half* dst = (is_mem ? g_memh : g_xh) + (size_t)row * DIM;
    uint2* d2 = reinterpret_cast<uint2*>(dst);
    #pragma unroll
    for (int j = 0; j < 8; j++) {
        __half2 p0 = __floats2half2_rn(v[j].x * iv, v[j].y * iv);
        __half2 p1 = __floats2half2_rn(v[j].z * iv, v[j].w * iv);
        uint2 w;
        w.x = *reinterpret_cast<uint32_t*>(&p0);
        w.y = *reinterpret_cast<uint32_t*>(&p1);
        d2[lane + 32 * j] = w;
    }
}

// ---------------- hybrid GEMM (HMMA 128 cols + HFMA2 64 cols) + top-8 ----------------
__global__ __launch_bounds__(256, 1) void gemm_topk_kernel() {
    extern __shared__ __align__(1024) char smem[];
    const uint32_t su = (uint32_t)__cvta_generic_to_shared(smem);
    const int tid = threadIdx.x;
    const int bm = blockIdx.x;   // fast dim -> CTAs sharing B tiles run together
    const int bn = blockIdx.y;

    // ---- A/B cp.async addressing (R2-proven layout) ----
    const int r0 = tid >> 2;
    const int ch = tid & 3;
    const __half* gA0 = g_xh + ((size_t)(bm * BM + r0)      * DIM + ch * 8);
    const __half* gA1 = g_xh + ((size_t)(bm * BM + r0 + 64) * DIM + ch * 8);
    size_t br0 = (size_t)bn * BNC + r0;        if (br0 >= C_ROWS) br0 = C_ROWS - 1;
    size_t br1 = (size_t)bn * BNC + r0 + 64;   if (br1 >= C_ROWS) br1 = C_ROWS - 1;
    const __half* gB0 = g_memh + br0 * DIM + ch * 8;
    const __half* gB1 = g_memh + br1 * DIM + ch * 8;
    const uint32_t sa0 = (r0 * SROW + ch * 8) * 2;
    const uint32_t sa1 = ((r0 + 64) * SROW + ch * 8) * 2;

    // ---- B' (SIMT) addressing ----
    const int bpn = tid >> 2;            // n 0..63
    const int bpk = tid & 3;             // k-quarter
    size_t bpr = (size_t)bn * BNC + BNT + bpn;
    if (bpr >= C_ROWS) bpr = C_ROWS - 1;
    const uint4* gBp = reinterpret_cast<const uint4*>(g_memh) + bpr * (DIM / 8) + bpk;

    // ---- HMMA accumulators & mapping ----
    const int lane = tid & 31;
    const int wm = ((tid >> 5) & 1) * 64;
    const int wn = (tid >> 6) * 32;
    float acc[4][4][4];
    #pragma unroll
    for (int i = 0; i < 4; i++)
        #pragma unroll
        for (int j = 0; j < 4; j++)
            #pragma unroll
            for (int q = 0; q < 4; q++) acc[i][j][q] = 0.f;

    // ---- SIMT accumulators & mapping ----
    const int tx = tid & 15;             // n0 = tx*4
    const int ty = tid >> 4;             // m0 = ty*8
    const int m0 = ty * 8;
    __half2 sacc[8][4];
    #pragma unroll
    for (int i = 0; i < 8; i++)
        #pragma unroll
        for (int j = 0; j < 4; j++) sacc[i][j] = __floats2half2_rn(0.f, 0.f);

    // ---- prologue: stage 0 ----
    {
        uint32_t base = su;
        cp16(base + sa0, gA0);
        cp16(base + sa1, gA1);
        cp16(base + AB_BYTES + sa0, gB0);
        cp16(base + AB_BYTES + sa1, gB1);
        cp_commit();
        uint4 bq = gBp[0];
        uint32_t pb = su + 2 * AB_BYTES;
        sts32(pb + (bpk * 4 + 0) * 256 + bpn * 4, bq.x);
        sts32(pb + (bpk * 4 + 1) * 256 + bpn * 4, bq.y);
        sts32(pb + (bpk * 4 + 2) * 256 + bpn * 4, bq.z);
        sts32(pb + (bpk * 4 + 3) * 256 + bpn * 4, bq.w);
    }

    for (int it = 0; it < NKI; ++it) {
        uint4 bqn;
        if (it + 1 < NKI) {
            uint32_t base = su + ((it + 1) & 1) * STAGE;
            size_t koff = (size_t)(it + 1) * BK;
            cp16(base + sa0, gA0 + koff);
            cp16(base + sa1, gA1 + koff);
            cp16(base + AB_BYTES + sa0, gB0 + koff);
            cp16(base + AB_BYTES + sa1, gB1 + koff);
            cp_commit();
            bqn = gBp[(it + 1) * 4];
            asm volatile("cp.async.wait_group 1;");
        } else {
            asm volatile("cp.async.wait_group 0;");
        }
        __syncthreads();

        uint32_t abase = su + (it & 1) * STAGE;
        uint32_t bbase = abase + AB_BYTES;
        uint32_t pbase = abase + 2 * AB_BYTES;

        #pragma unroll
        for (int kb = 0; kb < 2; ++kb) {
            // --- HMMA sub-block (k16) ---
            uint32_t a[4][4];
            #pragma unroll
            for (int mi = 0; mi < 4; ++mi) {
                uint32_t ad = abase +
                    ((wm + mi * 16 + (lane & 15)) * SROW + kb * 16 + (lane >> 4) * 8) * 2;
                ldsm4(a[mi], ad);
            }
            uint32_t bfr[4][2];
            #pragma unroll
            for (int bp = 0; bp < 2; ++bp) {
                int mat = lane >> 3;
                uint32_t bd = bbase +
                    ((wn + bp * 16 + (mat >> 1) * 8 + (lane & 7)) * SROW +
                     kb * 16 + (mat & 1) * 8) * 2;
                uint32_t r[4];
                ldsm4(r, bd);
                bfr[bp * 2 + 0][0] = r[0]; bfr[bp * 2 + 0][1] = r[1];
                bfr[bp * 2 + 1][0] = r[2]; bfr[bp * 2 + 1][1] = r[3];
            }
            #pragma unroll
            for (int mi = 0; mi < 4; ++mi)
                #pragma unroll
                for (int ni = 0; ni < 4; ++ni)
                    mma16816(acc[mi][ni], a[mi], bfr[ni][0], bfr[ni][1]);

            // --- SIMT sub-block (8 k2 steps = same k16 range) ---
            #pragma unroll
            for (int k2 = kb * 8; k2 < kb * 8 + 8; ++k2) {
                uint4 bq = lds128(pbase + k2 * 256 + tx * 16);
                __half2 bh[4] = {u2h2(bq.x), u2h2(bq.y), u2h2(bq.z), u2h2(bq.w)};
                #pragma unroll
                for (int i = 0; i < 8; ++i) {
                    __half2 ah = u2h2(lds32(abase + (m0 + i) * (SROW * 2) + k2 * 4));
                    #pragma unroll
                    for (int j = 0; j < 4; ++j)
                        sacc[i][j] = __hfma2(ah, bh[j], sacc[i][j]);
                }
            }
        }

        if (it + 1 < NKI) {
            uint32_t pb = su + ((it + 1) & 1) * STAGE + 2 * AB_BYTES;
            sts32(pb + (bpk * 4 + 0) * 256 + bpn * 4, bqn.x);
            sts32(pb + (bpk * 4 + 1) * 256 + bpn * 4, bqn.y);
            sts32(pb + (bpk * 4 + 2) * 256 + bpn * 4, bqn.z);
            sts32(pb + (bpk * 4 + 3) * 256 + bpn * 4, bqn.w);
        }
        __syncthreads();
    }

    // ---- epilogue: sims to smem ----
    float* Cs = reinterpret_cast<float*>(smem);
    #pragma unroll
    for (int mi = 0; mi < 4; ++mi) {
        #pragma unroll
        for (int ni = 0; ni < 4; ++ni) {
            int rb = wm + mi * 16 + (lane >> 2);
            int cb = wn + ni * 8 + (lane & 3) * 2;
            Cs[rb * CSTR + cb]           = acc[mi][ni][0];
            Cs[rb * CSTR + cb + 1]       = acc[mi][ni][1];
            Cs[(rb + 8) * CSTR + cb]     = acc[mi][ni][2];
            Cs[(rb + 8) * CSTR + cb + 1] = acc[mi][ni][3];
        }
    }
    #pragma unroll
    for (int i = 0; i < 8; ++i)
        #pragma unroll
        for (int j = 0; j < 4; ++j) {
            float v = __low2float(sacc[i][j]) + __high2float(sacc[i][j]);
            Cs[(m0 + i) * CSTR + BNT + tx * 4 + j] = v;
        }
    __syncthreads();

    // ---- per-row top-8 over 192 cols (with tail-validity mask) ----
    if (tid < BM) {
        const float* rowp = Cs + tid * CSTR;
        const int cbase = bn * BNC;
        float tv[CAND_PER_TILE];
        int   tc[CAND_PER_TILE];
        #pragma unroll
        for (int i = 0; i < CAND_PER_TILE; i++) { tv[i] = -1e30f; tc[i] = 0; }
        for (int c = 0; c < BNC; ++c) {
            float v = (cbase + c < C_ROWS) ? rowp[c] : -1e30f;
            if (v > tv[CAND_PER_TILE - 1]) {
                int p = CAND_PER_TILE - 1;
                while (p > 0 && v > tv[p - 1]) { tv[p] = tv[p - 1]; tc[p] = tc[p - 1]; --p; }
                tv[p] = v; tc[p] = c;
            }
        }
        size_t base = ((size_t)(bm * BM + tid) * NT + bn) * CAND_PER_TILE;
        #pragma unroll
        for (int i = 0; i < CAND_PER_TILE; i++) {
            g_cv[base + i] = tv[i];
            g_ci[base + i] = cbase + tc[i];
        }
    }
}

// ---------------- phase 2: exact rescore, top-5, softmax, weighted gather ----------------
__global__ __launch_bounds__(256) void rescore_out_kernel(const float* __restrict__ x,
                                                          const float* __restrict__ mem,
                                                          float* __restrict__ out) {
    const int row = blockIdx.x;
    const int tid = threadIdx.x, lane = tid & 31, warp = tid >> 5;
    __shared__ float sv[CAND_PER_ROW];
    __shared__ float wv[8];
    __shared__ int   wp[8];
    __shared__ int   cpos[RESCORE];
    __shared__ float ev[RESCORE];
    __shared__ int   em[RESCORE];
    __shared__ float wgt[TOPK];
    __shared__ int   sidx[TOPK];

    const float4* cv4 = reinterpret_cast<const float4*>(g_cv + (size_t)row * CAND_PER_ROW);
    float4* sv4 = reinterpret_cast<float4*>(sv);
    for (int j = tid; j < CAND_PER_ROW / 4; j += 256) sv4[j] = cv4[j];
    __syncthreads();

    for (int i = 0; i < RESCORE; ++i) {
        float best = -1e30f; int bp = -1;
        for (int j = tid; j < CAND_PER_ROW; j += 256) {
            float v = sv[j];
            if (v > best) { best = v; bp = j; }
        }
        #pragma unroll
        for (int o = 16; o; o >>= 1) {
            float ov = __shfl_down_sync(0xffffffffu, best, o);
            int   op = __shfl_down_sync(0xffffffffu, bp, o);
            if (ov > best) { best = ov; bp = op; }
        }
        if (lane == 0) { wv[warp] = best; wp[warp] = bp; }
        __syncthreads();
        if (tid == 0) {
            float bb = wv[0]; int pp = wp[0];
            #pragma unroll
            for (int w2 = 1; w2 < 8; w2++) if (wv[w2] > bb) { bb = wv[w2]; pp = wp[w2]; }
            cpos[i] = pp;
            sv[pp] = -1e30f;
        }
        __syncthreads();
    }

    const float4* xr = reinterpret_cast<const float4*>(x + (size_t)row * DIM);
    for (int i = warp; i < RESCORE; i += 8) {
        int mi = g_ci[(size_t)row * CAND_PER_ROW + cpos[i]];
        const float4* mr = reinterpret_cast<const float4*>(mem + (size_t)mi * DIM);
        float s = 0.f;
        for (int j = lane; j < DIM / 4; j += 32) {
            float4 a = xr[j], b = mr[j];
            s += a.x * b.x + a.y * b.y + a.z * b.z + a.w * b.w;
        }
        #pragma unroll
        for (int o = 16; o; o >>= 1) s += __shfl_down_sync(0xffffffffu, s, o);
        if (lane == 0) { ev[i] = s * g_minv[mi] * g_xinv[row]; em[i] = mi; }
    }
    __syncthreads();

    if (tid == 0) {
        bool used[RESCORE];
        #pragma unroll
        for (int i = 0; i < RESCORE; i++) used[i] = false;
        float tv[TOPK]; int ti[TOPK];
        #pragma unroll
        for (int r = 0; r < TOPK; ++r) {
            float bb = -1e30f; int pp = 0;
            for (int i = 0; i < RESCORE; i++)
                if (!used[i] && ev[i] > bb) { bb = ev[i]; pp = i; }
            used[pp] = true; tv[r] = bb; ti[r] = pp;
        }
        float mx = tv[0];
        float e[TOPK], se = 0.f;
        #pragma unroll
        for (int i = 0; i < TOPK; i++) { e[i] = expf(tv[i] - mx); se += e[i]; }
        #pragma unroll
        for (int i = 0; i < TOPK; i++) { wgt[i] = e[i] / se; sidx[i] = em[ti[i]]; }
    }
    __syncthreads();

    float4 accv = make_float4(0.f, 0.f, 0.f, 0.f);
    #pragma unroll
    for (int i = 0; i < TOPK; i++) {
        const float4* mr = reinterpret_cast<const float4*>(mem + (size_t)sidx[i] * DIM);
        float4 m = mr[tid];
        float wg = wgt[i];
        accv.x += wg * m.x; accv.y += wg * m.y; accv.z += wg * m.z; accv.w += wg * m.w;
    }
    reinterpret_cast<float4*>(out + (size_t)row * DIM)[tid] = accv;
}

// ---------------- launch ----------------
extern "C" void kernel_launch(void* const* d_in, const int* in_sizes, int n_in,
                              void* d_out, int out_size) {
    const float* x   = (const float*)d_in[0];
    const float* mem = (const float*)d_in[1];
    float* out = (float*)d_out;

    cudaFuncSetAttribute(gemm_topk_kernel,
                         cudaFuncAttributeMaxDynamicSharedMemorySize, SMEM_BYTES);

    prep_all_kernel<<<(C_ROWS + B_ROWS) / 8, 256>>>(mem, x);
    gemm_topk_kernel<<<dim3(B_ROWS / BM, NT), 256, SMEM_BYTES>>>();
    rescore_out_kernel<<<B_ROWS, 256>>>(x, mem, out);
}

// round 10
// speedup vs baseline: 1.8937x; 1.8937x over previous
#include <cuda_runtime.h>
#include <cuda_bf16.h>
#include <cstdint>
#include <cstddef>

// ---------------- problem constants ----------------
#define B_ROWS 4096
#define C_ROWS 65536
#define DIM    1024
#define TOPK   5

// ---------------- GEMM tiling (proven R2 config) ----------------
#define BM 128
#define BN 128
#define BK 32
#define NTILES (C_ROWS / BN)          // 512
#define CAND_PER_TILE 8
#define CAND_PER_ROW (NTILES * CAND_PER_TILE)  // 4096
#define RESCORE 16

#define SROW 40
#define STAGE_BYTES (2 * BM * SROW * 2)        // 20480
#define CS_STRIDE 129
#define SMEM_BYTES (BM * CS_STRIDE * 4)        // 66048

// ---------------- device scratch ----------------
__device__ __align__(16) __nv_bfloat16 g_memb[(size_t)C_ROWS * DIM]; // normalized bf16
__device__ __align__(16) __nv_bfloat16 g_xb[(size_t)B_ROWS * DIM];   // raw bf16
__device__ float g_minv[C_ROWS];
__device__ float g_xinv[B_ROWS];
__device__ __align__(16) float g_cv[(size_t)B_ROWS * CAND_PER_ROW];
__device__ __align__(16) int   g_ci[(size_t)B_ROWS * CAND_PER_ROW];

// ---------------- PTX helpers ----------------
__device__ __forceinline__ void cp16(uint32_t saddr, const void* gaddr) {
    asm volatile("cp.async.cg.shared.global [%0], [%1], 16;" :: "r"(saddr), "l"(gaddr));
}
__device__ __forceinline__ void cp_commit() {
    asm volatile("cp.async.commit_group;" ::: "memory");
}
__device__ __forceinline__ void ldsm4(uint32_t (&r)[4], uint32_t addr) {
    asm volatile("ldmatrix.sync.aligned.m8n8.x4.shared.b16 {%0,%1,%2,%3}, [%4];"
                 : "=r"(r[0]), "=r"(r[1]), "=r"(r[2]), "=r"(r[3]) : "r"(addr));
}
__device__ __forceinline__ void mma16816(float (&c)[4], const uint32_t (&a)[4],
                                         uint32_t b0, uint32_t b1) {
    asm volatile(
        "mma.sync.aligned.m16n8k16.row.col.f32.bf16.bf16.f32 "
        "{%0,%1,%2,%3},{%4,%5,%6,%7},{%8,%9},{%0,%1,%2,%3};"
        : "+f"(c[0]), "+f"(c[1]), "+f"(c[2]), "+f"(c[3])
        : "r"(a[0]), "r"(a[1]), "r"(a[2]), "r"(a[3]), "r"(b0), "r"(b1));
}

// ---------------- fused prep: warp-per-row, single launch (measured 56us) ----------------
__global__ __launch_bounds__(256) void prep_all_kernel(const float* __restrict__ mem,
                                                       const float* __restrict__ x) {
    const int gw = blockIdx.x * 8 + (threadIdx.x >> 5);   // global warp id
    const int lane = threadIdx.x & 31;
    const bool is_mem = (gw < C_ROWS);
    const int row = is_mem ? gw : gw - C_ROWS;
    if (!is_mem && row >= B_ROWS) return;

    const float* src = is_mem ? (mem + (size_t)row * DIM) : (x + (size_t)row * DIM);
    const float4* s4 = reinterpret_cast<const float4*>(src);

    float4 v[8];
    float ss = 0.f;
    #pragma unroll
    for (int j = 0; j < 8; j++) {
        v[j] = s4[lane + 32 * j];
        ss += v[j].x * v[j].x + v[j].y * v[j].y + v[j].z * v[j].z + v[j].w * v[j].w;
    }
    #pragma unroll
    for (int o = 16; o; o >>= 1) ss += __shfl_xor_sync(0xffffffffu, ss, o);
    float iv = 1.0f / fmaxf(sqrtf(ss), 1e-12f);
    if (lane == 0) {
        if (is_mem) g_minv[row] = iv;
        else        g_xinv[row] = iv;
    }
    float sc = is_mem ? iv : 1.0f;   // fold inv-norm into memory only (x scale rank-invariant)
    __nv_bfloat16* dst = (is_mem ? g_memb : g_xb) + (size_t)row * DIM;
    uint2* d2 = reinterpret_cast<uint2*>(dst);
    #pragma unroll
    for (int j = 0; j < 8; j++) {
        __nv_bfloat162 p0 = __floats2bfloat162_rn(v[j].x * sc, v[j].y * sc);
        __nv_bfloat162 p1 = __floats2bfloat162_rn(v[j].z * sc, v[j].w * sc);
        uint2 w;
        w.x = *reinterpret_cast<uint32_t*>(&p0);
        w.y = *reinterpret_cast<uint32_t*>(&p1);
        d2[lane + 32 * j] = w;
    }
}

// ---------------- coarse GEMM (bf16 HMMA, proven R2) + per-tile top-8 ----------------
__global__ __launch_bounds__(256) void gemm_topk_kernel() {
    extern __shared__ char smem[];
    const int tid = threadIdx.x;
    const int bm = blockIdx.x;   // fast dim -> consecutive CTAs share B tile in L2
    const int bn = blockIdx.y;
    const uint32_t smem_u = (uint32_t)__cvta_generic_to_shared(smem);

    const int r0 = tid >> 2;
    const int ch = tid & 3;
    const __nv_bfloat16* gA0 = g_xb   + ((size_t)(bm * BM + r0)      * DIM + ch * 8);
    const __nv_bfloat16* gA1 = g_xb   + ((size_t)(bm * BM + r0 + 64) * DIM + ch * 8);
    const __nv_bfloat16* gB0 = g_memb + ((size_t)(bn * BN + r0)      * DIM + ch * 8);
    const __nv_bfloat16* gB1 = g_memb + ((size_t)(bn * BN + r0 + 64) * DIM + ch * 8);

    const uint32_t sa0 = (r0 * SROW + ch * 8) * 2;
    const uint32_t sa1 = ((r0 + 64) * SROW + ch * 8) * 2;

    float acc[4][4][4];
    #pragma unroll
    for (int i = 0; i < 4; i++)
        #pragma unroll
        for (int j = 0; j < 4; j++)
            #pragma unroll
            for (int q = 0; q < 4; q++) acc[i][j][q] = 0.f;

    const int lane = tid & 31;
    const int wm = ((tid >> 5) & 1) * 64;
    const int wn = (tid >> 6) * 32;

    {
        uint32_t base = smem_u;
        cp16(base + sa0, gA0);
        cp16(base + sa1, gA1);
        cp16(base + BM * SROW * 2 + sa0, gB0);
        cp16(base + BM * SROW * 2 + sa1, gB1);
        cp_commit();
    }

    const int NK = DIM / BK;  // 32
    for (int it = 0; it < NK; ++it) {
        if (it + 1 < NK) {
            uint32_t base = smem_u + ((it + 1) & 1) * STAGE_BYTES;
            size_t koff = (size_t)(it + 1) * BK;
            cp16(base + sa0, gA0 + koff);
            cp16(base + sa1, gA1 + koff);
            cp16(base + BM * SROW * 2 + sa0, gB0 + koff);
            cp16(base + BM * SROW * 2 + sa1, gB1 + koff);
            cp_commit();
            asm volatile("cp.async.wait_group 1;");
        } else {
            asm volatile("cp.async.wait_group 0;");
        }
        __syncthreads();

        uint32_t abase = smem_u + (it & 1) * STAGE_BYTES;
        uint32_t bbase = abase + BM * SROW * 2;
        #pragma unroll
        for (int kb = 0; kb < 2; ++kb) {
            uint32_t a[4][4];
            #pragma unroll
            for (int mi = 0; mi < 4; ++mi) {
                uint32_t ad = abase +
                    ((wm + mi * 16 + (lane & 15)) * SROW + kb * 16 + (lane >> 4) * 8) * 2;
                ldsm4(a[mi], ad);
            }
            uint32_t bfr[4][2];
            #pragma unroll
            for (int bp = 0; bp < 2; ++bp) {
                int mat = lane >> 3;
                uint32_t bd = bbase +
                    ((wn + bp * 16 + (mat >> 1) * 8 + (lane & 7)) * SROW +
                     kb * 16 + (mat & 1) * 8) * 2;
                uint32_t r[4];
                ldsm4(r, bd);
                bfr[bp * 2 + 0][0] = r[0]; bfr[bp * 2 + 0][1] = r[1];
                bfr[bp * 2 + 1][0] = r[2]; bfr[bp * 2 + 1][1] = r[3];
            }
            #pragma unroll
            for (int mi = 0; mi < 4; ++mi)
                #pragma unroll
                for (int ni = 0; ni < 4; ++ni)
                    mma16816(acc[mi][ni], a[mi], bfr[ni][0], bfr[ni][1]);
        }
        __syncthreads();
    }

    // epilogue: dump sims to smem, per-row top-8
    float* Cs = reinterpret_cast<float*>(smem);
    #pragma unroll
    for (int mi = 0; mi < 4; ++mi) {
        #pragma unroll
        for (int ni = 0; ni < 4; ++ni) {
            int rb = wm + mi * 16 + (lane >> 2);
            int cb = wn + ni * 8 + (lane & 3) * 2;
            Cs[rb * CS_STRIDE + cb]             = acc[mi][ni][0];
            Cs[rb * CS_STRIDE + cb + 1]         = acc[mi][ni][1];
            Cs[(rb + 8) * CS_STRIDE + cb]       = acc[mi][ni][2];
            Cs[(rb + 8) * CS_STRIDE + cb + 1]   = acc[mi][ni][3];
        }
    }
    __syncthreads();

    if (tid < BM) {
        const float* rowp = Cs + tid * CS_STRIDE;
        float tv[CAND_PER_TILE];
        int   tc[CAND_PER_TILE];
        #pragma unroll
        for (int i = 0; i < CAND_PER_TILE; i++) { tv[i] = -1e30f; tc[i] = 0; }
        for (int c = 0; c < BN; ++c) {
            float v = rowp[c];
            if (v > tv[CAND_PER_TILE - 1]) {
                int p = CAND_PER_TILE - 1;
                while (p > 0 && v > tv[p - 1]) { tv[p] = tv[p - 1]; tc[p] = tc[p - 1]; --p; }
                tv[p] = v; tc[p] = c;
            }
        }
        size_t base = ((size_t)(bm * BM + tid) * NTILES + bn) * CAND_PER_TILE;
        #pragma unroll
        for (int i = 0; i < CAND_PER_TILE; i++) {
            g_cv[base + i] = tv[i];
            g_ci[base + i] = bn * BN + tc[i];
        }
    }
}

// ---------------- phase 2: exact rescore, top-5, softmax, weighted gather ----------------
__global__ __launch_bounds__(256) void rescore_out_kernel(const float* __restrict__ x,
                                                          const float* __restrict__ mem,
                                                          float* __restrict__ out) {
    const int row = blockIdx.x;
    const int tid = threadIdx.x, lane = tid & 31, warp = tid >> 5;
    __shared__ float sv[CAND_PER_ROW];
    __shared__ float wv[8];
    __shared__ int   wp[8];
    __shared__ int   cpos[RESCORE];
    __shared__ float ev[RESCORE];
    __shared__ int   em[RESCORE];
    __shared__ float wgt[TOPK];
    __shared__ int   sidx[TOPK];

    const float4* cv4 = reinterpret_cast<const float4*>(g_cv + (size_t)row * CAND_PER_ROW);
    float4* sv4 = reinterpret_cast<float4*>(sv);
    for (int j = tid; j < CAND_PER_ROW / 4; j += 256) sv4[j] = cv4[j];
    __syncthreads();

    // approx top-16 by coarse score (iterative extract-max)
    for (int i = 0; i < RESCORE; ++i) {
        float best = -1e30f; int bp = -1;
        for (int j = tid; j < CAND_PER_ROW; j += 256) {
            float v = sv[j];
            if (v > best) { best = v; bp = j; }
        }
        #pragma unroll
        for (int o = 16; o; o >>= 1) {
            float ov = __shfl_down_sync(0xffffffffu, best, o);
            int   op = __shfl_down_sync(0xffffffffu, bp, o);
            if (ov > best) { best = ov; bp = op; }
        }
        if (lane == 0) { wv[warp] = best; wp[warp] = bp; }
        __syncthreads();
        if (tid == 0) {
            float bb = wv[0]; int pp = wp[0];
            #pragma unroll
            for (int w2 = 1; w2 < 8; w2++) if (wv[w2] > bb) { bb = wv[w2]; pp = wp[w2]; }
            cpos[i] = pp;
            sv[pp] = -1e30f;
        }
        __syncthreads();
    }

    // exact fp32 rescore of 16 candidates (2 per warp)
    const float4* xr = reinterpret_cast<const float4*>(x + (size_t)row * DIM);
    for (int i = warp; i < RESCORE; i += 8) {
        int mi = g_ci[(size_t)row * CAND_PER_ROW + cpos[i]];
        const float4* mr = reinterpret_cast<const float4*>(mem + (size_t)mi * DIM);
        float s = 0.f;
        for (int j = lane; j < DIM / 4; j += 32) {
            float4 a = xr[j], b = mr[j];
            s += a.x * b.x + a.y * b.y + a.z * b.z + a.w * b.w;
        }
        #pragma unroll
        for (int o = 16; o; o >>= 1) s += __shfl_down_sync(0xffffffffu, s, o);
        if (lane == 0) { ev[i] = s * g_minv[mi] * g_xinv[row]; em[i] = mi; }
    }
    __syncthreads();

    if (tid == 0) {
        bool used[RESCORE];
        #pragma unroll
        for (int i = 0; i < RESCORE; i++) used[i] = false;
        float tv[TOPK]; int ti[TOPK];
        #pragma unroll
        for (int r = 0; r < TOPK; ++r) {
            float bb = -1e30f; int pp = 0;
            for (int i = 0; i < RESCORE; i++)
                if (!used[i] && ev[i] > bb) { bb = ev[i]; pp = i; }
            used[pp] = true; tv[r] = bb; ti[r] = pp;
        }
        float mx = tv[0];
        float e[TOPK], se = 0.f;
        #pragma unroll
        for (int i = 0; i < TOPK; i++) { e[i] = expf(tv[i] - mx); se += e[i]; }
        #pragma unroll
        for (int i = 0; i < TOPK; i++) { wgt[i] = e[i] / se; sidx[i] = em[ti[i]]; }
    }
    __syncthreads();

    // weighted gather of raw memory rows
    float4 accv = make_float4(0.f, 0.f, 0.f, 0.f);
    #pragma unroll
    for (int i = 0; i < TOPK; i++) {
        const float4* mr = reinterpret_cast<const float4*>(mem + (size_t)sidx[i] * DIM);
        float4 m = mr[tid];
        float wg = wgt[i];
        accv.x += wg * m.x; accv.y += wg * m.y; accv.z += wg * m.z; accv.w += wg * m.w;
    }
    reinterpret_cast<float4*>(out + (size_t)row * DIM)[tid] = accv;
}

// ---------------- launch ----------------
extern "C" void kernel_launch(void* const* d_in, const int* in_sizes, int n_in,
                              void* d_out, int out_size) {
    const float* x   = (const float*)d_in[0];
    const float* mem = (const float*)d_in[1];
    float* out = (float*)d_out;

    cudaFuncSetAttribute(gemm_topk_kernel,
                         cudaFuncAttributeMaxDynamicSharedMemorySize, SMEM_BYTES);

    prep_all_kernel<<<(C_ROWS + B_ROWS) / 8, 256>>>(mem, x);
    gemm_topk_kernel<<<dim3(B_ROWS / BM, NTILES), 256, SMEM_BYTES>>>();
    rescore_out_kernel<<<B_ROWS, 256>>>(x, mem, out);
}